// round 2
// baseline (speedup 1.0000x reference)
#include <cuda_runtime.h>

// Problem constants (match reference)
#define B_ROWS   65536
#define N_SPARSE 26
#define VOCAB    5000
#define N_DENSE  13

// One warp per batch row.
// sparse_idx is int32 on device (JAX downcasts int64 -> int32 without x64 mode).
// Lanes 0..25: load sparse_idx (coalesced 104B) + gather emb_table (L2-hot).
// Lanes 0..12: also accumulate dense[b, lane] * w[lane].
// Cross gathers: idx broadcast via shfl; lane 0 -> cross_table0, lane 1 -> cross_table1.
// Butterfly reduce; lane 0 writes out[b].

__global__ __launch_bounds__(256) void wide_kernel(
    const float* __restrict__ dense,        // [B, 13]
    const float* __restrict__ emb_table,    // [26, 5000]
    const float* __restrict__ cross_table0, // [25e6]
    const float* __restrict__ cross_table1, // [25e6]
    const float* __restrict__ dense_w,      // [13]
    const int*   __restrict__ sparse_idx,   // [B, 26] int32
    float*       __restrict__ out)          // [B]
{
    const int warps_per_block = blockDim.x >> 5;
    const int warp_in_block   = threadIdx.x >> 5;
    const int lane            = threadIdx.x & 31;
    const int row             = blockIdx.x * warps_per_block + warp_in_block;
    if (row >= B_ROWS) return;

    float acc = 0.0f;

    // Sparse: coalesced idx load + per-feature embedding gather (L2-resident table)
    int idx = 0;
    if (lane < N_SPARSE) {
        idx = __ldg(&sparse_idx[row * N_SPARSE + lane]);
        acc = __ldg(&emb_table[lane * VOCAB + idx]);
    }

    // Dense dot: contiguous 52B row read, weights L2/L1-hot
    if (lane < N_DENSE) {
        acc += __ldg(&dense[row * N_DENSE + lane]) * __ldg(&dense_w[lane]);
    }

    // Cross features: broadcast the four needed indices across the warp
    int i0 = __shfl_sync(0xFFFFFFFFu, idx, 0);
    int i1 = __shfl_sync(0xFFFFFFFFu, idx, 1);
    int i2 = __shfl_sync(0xFFFFFFFFu, idx, 2);
    int i3 = __shfl_sync(0xFFFFFFFFu, idx, 3);
    if (lane == 0) acc += __ldg(&cross_table0[(long long)i0 * VOCAB + i1]);
    if (lane == 1) acc += __ldg(&cross_table1[(long long)i2 * VOCAB + i3]);

    // Warp reduction
    #pragma unroll
    for (int off = 16; off > 0; off >>= 1)
        acc += __shfl_xor_sync(0xFFFFFFFFu, acc, off);

    if (lane == 0) out[row] = acc;
}

extern "C" void kernel_launch(void* const* d_in, const int* in_sizes, int n_in,
                              void* d_out, int out_size)
{
    // Defensive pointer identification by element count (all sizes unique
    // except the two cross tables, which keep their relative order).
    const float* dense        = nullptr;
    const float* emb_table    = nullptr;
    const float* cross_table0 = nullptr;
    const float* cross_table1 = nullptr;
    const float* dense_w      = nullptr;
    const int*   sparse_idx   = nullptr;

    for (int i = 0; i < n_in; i++) {
        const long long sz = in_sizes[i];
        if      (sz == (long long)B_ROWS * N_DENSE)   dense      = (const float*)d_in[i];
        else if (sz == (long long)N_SPARSE * VOCAB)   emb_table  = (const float*)d_in[i];
        else if (sz == (long long)VOCAB * VOCAB) {
            if (!cross_table0) cross_table0 = (const float*)d_in[i];
            else               cross_table1 = (const float*)d_in[i];
        }
        else if (sz == N_DENSE)                       dense_w    = (const float*)d_in[i];
        else if (sz == (long long)B_ROWS * N_SPARSE)  sparse_idx = (const int*)d_in[i];
    }

    float* out = (float*)d_out;

    const int threads = 256;                  // 8 warps = 8 rows per block
    const int rows_per_block = threads / 32;
    const int blocks = (B_ROWS + rows_per_block - 1) / rows_per_block;
    wide_kernel<<<blocks, threads>>>(dense, emb_table, cross_table0, cross_table1,
                                     dense_w, sparse_idx, out);
}